// round 6
// baseline (speedup 1.0000x reference)
#include <cuda_runtime.h>
#include <cuda_bf16.h>
#include <math.h>

#define BB 2
#define TT 64
#define CC 384
#define HH 768
#define BKt 16
#define LDA_S 68

// ---------------- scratch (device globals) ----------------
// zeroed each call via one cudaMemsetAsync: [k | v | dp | h1 | ds]
#define N_KV   (BB*TT*CC)
#define N_H    (BB*TT*HH)
__device__ float g_scratch[3*N_KV + 2*N_H];
#define g_k  (g_scratch)
#define g_v  (g_scratch + N_KV)
#define g_dp (g_scratch + 2*N_KV)
#define g_h1 (g_scratch + 3*N_KV)
#define g_ds (g_scratch + 3*N_KV + N_H)

__device__ float g_q[CC];
__device__ float g_h[BB*HH];
__device__ float g_pred[BB*CC];

__device__ __forceinline__ float silu_f(float x) {
    float s = 1.f / (1.f + expf(-x)); return x * s;
}
__device__ __forceinline__ float gfac_f(float x) {
    float s = 1.f / (1.f + expf(-x)); return s * (1.f + x * (1.f - s));
}

__device__ __forceinline__ float warpdot4(const float4* a, const float4* b, int n4) {
    float s = 0.f;
    for (int i = (threadIdx.x & 31); i < n4; i += 32) {
        float4 x = a[i], y = b[i];
        s += x.x*y.x + x.y*y.y + x.z*y.z + x.w*y.w;
    }
    #pragma unroll
    for (int o = 16; o; o >>= 1) s += __shfl_xor_sync(0xFFFFFFFFu, s, o);
    return s;
}

__device__ __forceinline__ void core16(const float (*As)[LDA_S], const float (*Bs)[LDA_S],
                                       float (&acc)[4][4], int tm, int tn) {
    #pragma unroll
    for (int kk = 0; kk < BKt; ++kk) {
        float4 a4 = *(const float4*)&As[kk][tm*4];
        float4 b4 = *(const float4*)&Bs[kk][tn*4];
        float av[4] = {a4.x, a4.y, a4.z, a4.w};
        float bv[4] = {b4.x, b4.y, b4.z, b4.w};
        #pragma unroll
        for (int i = 0; i < 4; ++i)
            #pragma unroll
            for (int j = 0; j < 4; ++j)
                acc[i][j] += av[i] * bv[j];
    }
}

// scatter-transpose STS: thread owns (r, ks..ks+3); S[ks+i][r] = v
__device__ __forceinline__ void sts4(float (*S)[LDA_S], int r, int ks, float4 v) {
    S[ks+0][r] = v.x; S[ks+1][r] = v.y; S[ks+2][r] = v.z; S[ks+3][r] = v.w;
}

// ============================================================================
// K1: kv GEMM (192 blocks, splitK=8, K=48 each) + q (48 blocks)
// ============================================================================
__global__ void K1(const float* __restrict__ x, const float* __restrict__ Wk,
                   const float* __restrict__ Wv, const float* __restrict__ bk,
                   const float* __restrict__ bv, const float* __restrict__ iq,
                   const float* __restrict__ Wq, const float* __restrict__ bq) {
    int blk = blockIdx.x, tid = threadIdx.x;
    if (blk < 192) {
        __shared__ float As[2][BKt][LDA_S], Bs[2][BKt][LDA_S];
        int kc = blk & 7, tile = blk >> 3;
        int tr = tile / 12, tc = tile % 12;
        int m0 = tr*64, n0 = tc*64, k0 = kc*48;
        const float* Wn = (n0 < CC) ? Wk + (size_t)n0*CC : Wv + (size_t)(n0-CC)*CC;
        int r = tid >> 2, ks = (tid & 3) << 2;
        const float* pa = x  + (size_t)(m0 + r)*CC + k0 + ks;
        const float* pb = Wn + (size_t)r*CC       + k0 + ks;
        float4 ra = *(const float4*)pa, rb = *(const float4*)pb;
        sts4(As[0], r, ks, ra); sts4(Bs[0], r, ks, rb);
        __syncthreads();
        float acc[4][4] = {};
        int tm = tid & 15, tn = tid >> 4;
        #pragma unroll
        for (int kt = 0; kt < 3; ++kt) {
            if (kt < 2) { ra = *(const float4*)(pa + (kt+1)*BKt);
                          rb = *(const float4*)(pb + (kt+1)*BKt); }
            core16(As[kt&1], Bs[kt&1], acc, tm, tn);
            if (kt < 2) { sts4(As[(kt+1)&1], r, ks, ra); sts4(Bs[(kt+1)&1], r, ks, rb); }
            __syncthreads();
        }
        float* dst; int nb; const float* bias;
        if (n0 < CC) { dst = g_k; nb = n0;      bias = bk; }
        else         { dst = g_v; nb = n0 - CC; bias = bv; }
        #pragma unroll
        for (int i = 0; i < 4; ++i) {
            int m = m0 + tm*4 + i;
            #pragma unroll
            for (int j = 0; j < 4; ++j) {
                int c = nb + tn*4 + j;
                float add = acc[i][j] + (kc == 0 ? bias[c] : 0.f);
                atomicAdd(&dst[(size_t)m*CC + c], add);
            }
        }
    } else {  // q[c] = iq . Wq[c,:] + bq
        int w = (blk - 192)*8 + (tid >> 5);
        float s = warpdot4((const float4*)iq, (const float4*)(Wq + (size_t)w*CC), CC/4);
        if ((tid & 31) == 0) g_q[w] = s + bq[w];
    }
}

// ============================================================================
// K2: h1pre GEMM (192 blocks, splitK=8) + h retrieval (192 blocks)
// ============================================================================
__global__ void K2(const float* __restrict__ sW0, const float* __restrict__ sb0) {
    int blk = blockIdx.x, tid = threadIdx.x;
    if (blk < 192) {
        __shared__ float As[2][BKt][LDA_S], Bs[2][BKt][LDA_S];
        int kc = blk & 7, tile = blk >> 3;
        int bb = tile / 12, tc = tile % 12;
        int n0 = tc*64, k0 = kc*48;
        int r = tid >> 2, ks = (tid & 3) << 2;
        const float* pa = g_k + (size_t)(bb*TT + r)*CC + k0 + ks;
        const float* pb = sW0 + (size_t)(bb*HH + n0 + r)*CC + k0 + ks;
        float4 ra = *(const float4*)pa, rb = *(const float4*)pb;
        sts4(As[0], r, ks, ra); sts4(Bs[0], r, ks, rb);
        __syncthreads();
        float acc[4][4] = {};
        int tm = tid & 15, tn = tid >> 4;
        #pragma unroll
        for (int kt = 0; kt < 3; ++kt) {
            if (kt < 2) { ra = *(const float4*)(pa + (kt+1)*BKt);
                          rb = *(const float4*)(pb + (kt+1)*BKt); }
            core16(As[kt&1], Bs[kt&1], acc, tm, tn);
            if (kt < 2) { sts4(As[(kt+1)&1], r, ks, ra); sts4(Bs[(kt+1)&1], r, ks, rb); }
            __syncthreads();
        }
        #pragma unroll
        for (int i = 0; i < 4; ++i) {
            int m = tm*4 + i;
            #pragma unroll
            for (int j = 0; j < 4; ++j) {
                int h = n0 + tn*4 + j;
                float add = acc[i][j] + (kc == 0 ? sb0[bb*HH + h] : 0.f);
                atomicAdd(&g_h1[(size_t)(bb*TT + m)*HH + h], add);
            }
        }
    } else {  // h[b,h] = silu(q . sW0[b,h,:] + sb0)
        int w = (blk - 192)*8 + (tid >> 5);
        float s = warpdot4((const float4*)g_q, (const float4*)(sW0 + (size_t)w*CC), CC/4)
                  + sb0[w];
        if ((tid & 31) == 0) g_h[w] = silu_f(s);
    }
}

// ============================================================================
// K3: dp GEMM (192 blocks, splitK=16, K=48 each; A=silu(h1)) + pred (96 blocks)
// ============================================================================
__global__ void K3(const float* __restrict__ sW1, const float* __restrict__ sb1) {
    int blk = blockIdx.x, tid = threadIdx.x;
    if (blk < 192) {
        __shared__ float As[2][BKt][LDA_S], Bs[2][BKt][LDA_S];
        int kc = blk & 15, tile = blk >> 4;
        int bb = tile / 6, tc = tile % 6;
        int n0 = tc*64, k0 = kc*48;
        int r = tid >> 2, ks = (tid & 3) << 2;
        const float* pa = g_h1 + (size_t)(bb*TT + r)*HH + k0 + ks;
        const float* pb = sW1 + (size_t)(bb*CC + n0 + r)*HH + k0 + ks;
        float4 ra = *(const float4*)pa, rb = *(const float4*)pb;
        float4 sa = make_float4(silu_f(ra.x), silu_f(ra.y), silu_f(ra.z), silu_f(ra.w));
        sts4(As[0], r, ks, sa); sts4(Bs[0], r, ks, rb);
        __syncthreads();
        float acc[4][4] = {};
        int tm = tid & 15, tn = tid >> 4;
        #pragma unroll
        for (int kt = 0; kt < 3; ++kt) {
            if (kt < 2) { ra = *(const float4*)(pa + (kt+1)*BKt);
                          rb = *(const float4*)(pb + (kt+1)*BKt); }
            core16(As[kt&1], Bs[kt&1], acc, tm, tn);
            if (kt < 2) {
                float4 sa2 = make_float4(silu_f(ra.x), silu_f(ra.y), silu_f(ra.z), silu_f(ra.w));
                sts4(As[(kt+1)&1], r, ks, sa2); sts4(Bs[(kt+1)&1], r, ks, rb);
            }
            __syncthreads();
        }
        #pragma unroll
        for (int i = 0; i < 4; ++i) {
            int m = tm*4 + i;
            #pragma unroll
            for (int j = 0; j < 4; ++j) {
                int c = n0 + tn*4 + j;
                size_t idx = (size_t)(bb*TT + m)*CC + c;
                float add = acc[i][j]
                          + (kc == 0 ? (sb1[bb*CC + c] - g_v[idx]) : 0.f);
                atomicAdd(&g_dp[idx], add);
            }
        }
    } else {  // pred[b,c] = h . sW1[b,c,:] + sb1
        int w = (blk - 192)*8 + (tid >> 5);
        int b = w / CC;
        float s = warpdot4((const float4*)(g_h + b*HH),
                           (const float4*)(sW1 + (size_t)w*HH), HH/4) + sb1[w];
        if ((tid & 31) == 0) g_pred[w] = s;
    }
}

// ============================================================================
// K4: ds GEMM = dp @ sW1 (192 blocks, splitK=8, B loaded NN) + out (96 blocks)
// ============================================================================
__global__ void K4(const float* __restrict__ sW1, const float* __restrict__ Wo,
                   const float* __restrict__ bo, float* __restrict__ o_out) {
    int blk = blockIdx.x, tid = threadIdx.x;
    if (blk < 192) {
        __shared__ float As[2][BKt][LDA_S], Bs[2][BKt][LDA_S];
        int kc = blk & 7, tile = blk >> 3;
        int bb = tile / 12, tc = tile % 12;
        int n0 = tc*64, k0 = kc*48;
        int r = tid >> 2, ks = (tid & 3) << 2;       // A side: transpose load
        int kkb = tid >> 4, cs = (tid & 15) << 2;    // B side: NN load
        const float* pa = g_dp + (size_t)(bb*TT + r)*CC + k0 + ks;
        const float* pb = sW1 + (size_t)(bb*CC + k0 + kkb)*HH + n0 + cs;
        float4 ra = *(const float4*)pa, rb = *(const float4*)pb;
        sts4(As[0], r, ks, ra);
        *(float4*)&Bs[0][kkb][cs] = rb;
        __syncthreads();
        float acc[4][4] = {};
        int tm = tid & 15, tn = tid >> 4;
        #pragma unroll
        for (int kt = 0; kt < 3; ++kt) {
            if (kt < 2) { ra = *(const float4*)(pa + (kt+1)*BKt);
                          rb = *(const float4*)(pb + (size_t)(kt+1)*BKt*HH); }
            core16(As[kt&1], Bs[kt&1], acc, tm, tn);
            if (kt < 2) { sts4(As[(kt+1)&1], r, ks, ra);
                          *(float4*)&Bs[(kt+1)&1][kkb][cs] = rb; }
            __syncthreads();
        }
        #pragma unroll
        for (int i = 0; i < 4; ++i) {
            int m = tm*4 + i;
            #pragma unroll
            for (int j = 0; j < 4; ++j)
                atomicAdd(&g_ds[(size_t)(bb*TT + m)*HH + n0 + tn*4 + j], acc[i][j]);
        }
    } else {  // out[b,c] = pred . Wo[c,:] + bo
        int w = (blk - 192)*8 + (tid >> 5);
        int b = w / CC, c = w % CC;
        float s = warpdot4((const float4*)(g_pred + b*CC),
                           (const float4*)(Wo + (size_t)c*CC), CC/4) + bo[c];
        if ((tid & 31) == 0) o_out[w] = s;
    }
}

// ============================================================================
// K5: nw0 (144) + nw1 (144) + biases (9). K=T=64 (4 slabs), double-buffered.
// ============================================================================
__global__ void K5(const float* __restrict__ sW0, const float* __restrict__ sW1,
                   const float* __restrict__ sb0, const float* __restrict__ sb1,
                   float* __restrict__ o_nw0, float* __restrict__ o_nb0,
                   float* __restrict__ o_nw1, float* __restrict__ o_nb1) {
    __shared__ float As[2][BKt][LDA_S], Bs[2][BKt][LDA_S];
    __shared__ float coeff_s[TT];
    __shared__ float dfac_s;
    int blk = blockIdx.x, tid = threadIdx.x;
    if (tid < TT) {
        double d = 0.999, rr_ = 0.9 / 0.999;
        double cs = pow(d, (double)(TT-1-tid)) * (pow(rr_, (double)(TT-tid)) - 1.0) / (rr_ - 1.0);
        coeff_s[tid] = (float)(-0.01 * 0.1 * cs);
    }
    if (tid == TT) dfac_s = (float)pow(0.999, (double)TT);
    __syncthreads();

    if (blk < 288) {
        bool is0 = blk < 144;
        int tile = is0 ? blk : blk - 144;
        int bb = tile / 72, rr = tile % 72;
        int tr = is0 ? rr/6 : rr/12;
        int tc = is0 ? rr%6 : rr%12;
        int m0 = tr*64, n0 = tc*64;
        int kk = tid >> 4, ms = (tid & 15) << 2;
        float4 r1, r2, r3;
        // pointers for slab kt: t = kt*16 + kk
        #define LD_SLAB(kt) do {                                                   \
            int t_ = (kt)*BKt + kk;                                                \
            if (is0) {                                                             \
                size_t ia = (size_t)(bb*TT + t_)*HH + m0 + ms;                     \
                r1 = *(const float4*)&g_ds[ia];                                    \
                r2 = *(const float4*)&g_h1[ia];                                    \
                r3 = *(const float4*)&g_k[(size_t)(bb*TT + t_)*CC + n0 + ms];      \
            } else {                                                               \
                r1 = *(const float4*)&g_dp[(size_t)(bb*TT + t_)*CC + m0 + ms];     \
                r2 = *(const float4*)&g_h1[(size_t)(bb*TT + t_)*HH + n0 + ms];     \
            }                                                                      \
        } while (0)
        #define ST_SLAB(buf, kt) do {                                              \
            int t_ = (kt)*BKt + kk;                                                \
            float cf = coeff_s[t_];                                                \
            if (is0) {                                                             \
                As[buf][kk][ms+0] = cf * r1.x * gfac_f(r2.x);                      \
                As[buf][kk][ms+1] = cf * r1.y * gfac_f(r2.y);                      \
                As[buf][kk][ms+2] = cf * r1.z * gfac_f(r2.z);                      \
                As[buf][kk][ms+3] = cf * r1.w * gfac_f(r2.w);                      \
                *(float4*)&Bs[buf][kk][ms] = r3;                                   \
            } else {                                                               \
                As[buf][kk][ms+0] = cf * r1.x; As[buf][kk][ms+1] = cf * r1.y;      \
                As[buf][kk][ms+2] = cf * r1.z; As[buf][kk][ms+3] = cf * r1.w;      \
                Bs[buf][kk][ms+0] = silu_f(r2.x); Bs[buf][kk][ms+1] = silu_f(r2.y);\
                Bs[buf][kk][ms+2] = silu_f(r2.z); Bs[buf][kk][ms+3] = silu_f(r2.w);\
            }                                                                      \
        } while (0)
        LD_SLAB(0); ST_SLAB(0, 0);
        __syncthreads();
        float acc[4][4] = {};
        int tm = tid & 15, tn = tid >> 4;
        #pragma unroll
        for (int kt = 0; kt < 4; ++kt) {
            if (kt < 3) LD_SLAB(kt+1);
            core16(As[kt&1], Bs[kt&1], acc, tm, tn);
            if (kt < 3) ST_SLAB((kt+1)&1, kt+1);
            __syncthreads();
        }
        float df = dfac_s;
        if (is0) {
            #pragma unroll
            for (int i = 0; i < 4; ++i) {
                int h = m0 + tm*4 + i;
                #pragma unroll
                for (int j = 0; j < 4; ++j) {
                    size_t idx = (size_t)(bb*HH + h)*CC + n0 + tn*4 + j;
                    o_nw0[idx] = df * sW0[idx] + acc[i][j];
                }
            }
        } else {
            #pragma unroll
            for (int i = 0; i < 4; ++i) {
                int c = m0 + tm*4 + i;
                #pragma unroll
                for (int j = 0; j < 4; ++j) {
                    size_t idx = (size_t)(bb*CC + c)*HH + n0 + tn*4 + j;
                    o_nw1[idx] = df * sW1[idx] + acc[i][j];
                }
            }
        }
    } else {  // biases
        int i = (blk - 288)*256 + tid;
        float df = dfac_s;
        if (i < BB*HH) {
            int b = i / HH, h = i % HH;
            float acc = 0.f;
            #pragma unroll 8
            for (int t = 0; t < TT; ++t) {
                size_t idx = (size_t)(b*TT + t)*HH + h;
                acc += coeff_s[t] * g_ds[idx] * gfac_f(g_h1[idx]);
            }
            o_nb0[i] = df * sb0[i] + acc;
        } else if (i < BB*HH + BB*CC) {
            int j = i - BB*HH;
            int b = j / CC, c = j % CC;
            float acc = 0.f;
            #pragma unroll 8
            for (int t = 0; t < TT; ++t)
                acc += coeff_s[t] * g_dp[(size_t)(b*TT + t)*CC + c];
            o_nb1[j] = df * sb1[j] + acc;
        }
    }
}

// ============================================================================
extern "C" void kernel_launch(void* const* d_in, const int* in_sizes, int n_in,
                              void* d_out, int out_size) {
    const float* x   = (const float*)d_in[0];
    const float* Wq  = (const float*)d_in[1];
    const float* bq  = (const float*)d_in[2];
    const float* Wk  = (const float*)d_in[3];
    const float* bk  = (const float*)d_in[4];
    const float* Wv  = (const float*)d_in[5];
    const float* bv  = (const float*)d_in[6];
    const float* Wo  = (const float*)d_in[7];
    const float* bo  = (const float*)d_in[8];
    const float* iq  = (const float*)d_in[9];
    const float* sW0 = (const float*)d_in[10];
    const float* sb0 = (const float*)d_in[11];
    const float* sW1 = (const float*)d_in[12];
    const float* sb1 = (const float*)d_in[13];

    float* out   = (float*)d_out;
    float* o_out = out;
    float* o_nw0 = o_out + BB*CC;
    float* o_nb0 = o_nw0 + (size_t)BB*HH*CC;
    float* o_nw1 = o_nb0 + BB*HH;
    float* o_nb1 = o_nw1 + (size_t)BB*CC*HH;

    void* zbase = nullptr;
    cudaGetSymbolAddress(&zbase, g_scratch);
    cudaMemsetAsync(zbase, 0, (size_t)(3*N_KV + 2*N_H) * sizeof(float));

    K1<<<240, 256>>>(x, Wk, Wv, bk, bv, iq, Wq, bq);
    K2<<<384, 256>>>(sW0, sb0);
    K3<<<288, 256>>>(sW1, sb1);
    K4<<<288, 256>>>(sW1, Wo, bo, o_out);
    K5<<<297, 256>>>(sW0, sW1, sb0, sb1, o_nw0, o_nb0, o_nw1, o_nb1);
}

// round 7
// speedup vs baseline: 1.4519x; 1.4519x over previous
#include <cuda_runtime.h>
#include <cuda_bf16.h>
#include <math.h>

#define BB 2
#define TT 64
#define CC 384
#define HH 768
#define BKt 16
#define LDA_S 68
#define NB 288          // persistent grid size (must all be co-resident)
#define NWARPS (144*8)  // spare warps in S1-S3

// ---------------- scratch (device globals) ----------------
#define N_KV (BB*TT*CC)   // 49152
#define N_H  (BB*TT*HH)   // 98304
__device__ float g_k[N_KV];
__device__ float g_v[N_KV];
__device__ float g_dp[N_KV];   // holds p (= silu(h1)@W1 + sb1); consumers do p - v
__device__ float g_h1[N_H];    // layer-1 pre-activation (bias included)
__device__ float g_ds[N_H];    // dp @ W1
__device__ float g_q[CC];
__device__ float g_h[BB*HH];
__device__ float g_pred[BB*CC];
__device__ unsigned g_bar[8];  // monotonic ticket counters (never reset)

__device__ __forceinline__ float silu_f(float x) {
    float s = 1.f / (1.f + expf(-x)); return x * s;
}
__device__ __forceinline__ float gfac_f(float x) {
    float s = 1.f / (1.f + expf(-x)); return s * (1.f + x * (1.f - s));
}

__device__ __forceinline__ void grid_bar(int which) {
    __syncthreads();
    if (threadIdx.x == 0) {
        __threadfence();
        unsigned ticket = atomicAdd(&g_bar[which], 1u);
        unsigned target = ticket - (ticket % NB) + NB;
        while ((int)(*(volatile unsigned*)&g_bar[which] - target) < 0)
            __nanosleep(64);
    }
    __syncthreads();
}

__device__ __forceinline__ float warpdot4(const float4* a, const float4* b, int n4) {
    float s = 0.f;
    for (int i = (threadIdx.x & 31); i < n4; i += 32) {
        float4 x = a[i], y = b[i];
        s += x.x*y.x + x.y*y.y + x.z*y.z + x.w*y.w;
    }
    #pragma unroll
    for (int o = 16; o; o >>= 1) s += __shfl_xor_sync(0xFFFFFFFFu, s, o);
    return s;
}

__device__ __forceinline__ void core16(const float (*As)[LDA_S], const float (*Bs)[LDA_S],
                                       float (&acc)[4][4], int tm, int tn) {
    #pragma unroll
    for (int kk = 0; kk < BKt; ++kk) {
        float4 a4 = *(const float4*)&As[kk][tm*4];
        float4 b4 = *(const float4*)&Bs[kk][tn*4];
        float av[4] = {a4.x, a4.y, a4.z, a4.w};
        float bv[4] = {b4.x, b4.y, b4.z, b4.w};
        #pragma unroll
        for (int i = 0; i < 4; ++i)
            #pragma unroll
            for (int j = 0; j < 4; ++j)
                acc[i][j] += av[i] * bv[j];
    }
}

__device__ __forceinline__ void sts4(float (*S)[LDA_S], int r, int ks, float4 v) {
    S[ks+0][r] = v.x; S[ks+1][r] = v.y; S[ks+2][r] = v.z; S[ks+3][r] = v.w;
}

// ============================================================================
__global__ void __launch_bounds__(256, 2)
fused(const float* __restrict__ x,   const float* __restrict__ Wq,
      const float* __restrict__ bq,  const float* __restrict__ Wk,
      const float* __restrict__ bk,  const float* __restrict__ Wv,
      const float* __restrict__ bv,  const float* __restrict__ Wo,
      const float* __restrict__ bo,  const float* __restrict__ iq,
      const float* __restrict__ sW0, const float* __restrict__ sb0,
      const float* __restrict__ sW1, const float* __restrict__ sb1,
      float* __restrict__ o_out, float* __restrict__ o_nw0,
      float* __restrict__ o_nb0, float* __restrict__ o_nw1,
      float* __restrict__ o_nb1)
{
    __shared__ float As[2][BKt][LDA_S];
    __shared__ float Bs[2][BKt][LDA_S];
    __shared__ float red[TT];
    __shared__ float coeff_s[TT];

    const int bid = blockIdx.x, tid = threadIdx.x;
    const int gtid = bid*256 + tid;
    const int r  = tid >> 2, ks = (tid & 3) << 2;   // transpose-load role
    const int tm = tid & 15, tn = tid >> 4;          // micro-tile role

    // ---------------- S0: init scratch with biases + q ----------------
    for (int i = gtid; i < N_KV; i += NB*256) {
        int c = i % CC;
        g_k[i]  = bk[c];
        g_v[i]  = bv[c];
        g_dp[i] = sb1[(i/(TT*CC))*CC + c];
    }
    for (int i = gtid; i < N_H; i += NB*256) {
        g_h1[i] = sb0[(i/(TT*HH))*HH + (i % HH)];
        g_ds[i] = 0.f;
    }
    if (bid >= 240) {   // q: 384 dots, K=384
        int w = (bid - 240)*8 + (tid >> 5);
        float s = warpdot4((const float4*)iq, (const float4*)(Wq + (size_t)w*CC), CC/4);
        if ((tid & 31) == 0) g_q[w] = s + bq[w];
    }
    grid_bar(0);

    // ---------------- S1: kv GEMM (144) + h retrieval (144) ----------------
    if (bid < 144) {
        int kc = bid % 6, tile = bid / 6;
        int tr = tile / 12, tc = tile % 12;
        int m0 = tr*64, n0 = tc*64, k0 = kc*64;
        const float* Wn = (n0 < CC) ? Wk + (size_t)n0*CC : Wv + (size_t)(n0-CC)*CC;
        const float* pa = x  + (size_t)(m0 + r)*CC + k0 + ks;
        const float* pb = Wn + (size_t)r*CC       + k0 + ks;
        float4 ra = *(const float4*)pa, rb = *(const float4*)pb;
        sts4(As[0], r, ks, ra); sts4(Bs[0], r, ks, rb);
        __syncthreads();
        float acc[4][4] = {};
        #pragma unroll
        for (int kt = 0; kt < 4; ++kt) {
            if (kt < 3) { ra = *(const float4*)(pa + (kt+1)*BKt);
                          rb = *(const float4*)(pb + (kt+1)*BKt); }
            core16(As[kt&1], Bs[kt&1], acc, tm, tn);
            if (kt < 3) { sts4(As[(kt+1)&1], r, ks, ra); sts4(Bs[(kt+1)&1], r, ks, rb); }
            __syncthreads();
        }
        float* dst = (n0 < CC) ? g_k : g_v;
        int nb = (n0 < CC) ? n0 : n0 - CC;
        #pragma unroll
        for (int i = 0; i < 4; ++i) {
            int m = m0 + tm*4 + i;
            #pragma unroll
            for (int j = 0; j < 4; ++j)
                atomicAdd(&dst[(size_t)m*CC + nb + tn*4 + j], acc[i][j]);
        }
    } else {            // h: 1536 dots, K=384
        for (int w = (bid - 144)*8 + (tid >> 5); w < BB*HH; w += NWARPS) {
            float s = warpdot4((const float4*)g_q, (const float4*)(sW0 + (size_t)w*CC),
                               CC/4) + sb0[w];
            if ((tid & 31) == 0) g_h[w] = silu_f(s);
        }
    }
    grid_bar(1);

    // ---------------- S2: h1pre GEMM (144) + pred (spare) ----------------
    if (bid < 144) {
        int kc = bid % 6, tile = bid / 6;
        int bb = tile / 12, tc = tile % 12;
        int n0 = tc*64, k0 = kc*64;
        const float* pa = g_k + (size_t)(bb*TT + r)*CC + k0 + ks;
        const float* pb = sW0 + (size_t)(bb*HH + n0 + r)*CC + k0 + ks;
        float4 ra = *(const float4*)pa, rb = *(const float4*)pb;
        sts4(As[0], r, ks, ra); sts4(Bs[0], r, ks, rb);
        __syncthreads();
        float acc[4][4] = {};
        #pragma unroll
        for (int kt = 0; kt < 4; ++kt) {
            if (kt < 3) { ra = *(const float4*)(pa + (kt+1)*BKt);
                          rb = *(const float4*)(pb + (kt+1)*BKt); }
            core16(As[kt&1], Bs[kt&1], acc, tm, tn);
            if (kt < 3) { sts4(As[(kt+1)&1], r, ks, ra); sts4(Bs[(kt+1)&1], r, ks, rb); }
            __syncthreads();
        }
        #pragma unroll
        for (int i = 0; i < 4; ++i) {
            int m = tm*4 + i;
            #pragma unroll
            for (int j = 0; j < 4; ++j)
                atomicAdd(&g_h1[(size_t)(bb*TT + m)*HH + n0 + tn*4 + j], acc[i][j]);
        }
    } else {            // pred: 768 dots, K=768
        int w = (bid - 144)*8 + (tid >> 5);
        if (w < BB*CC) {
            int b = w / CC;
            float s = warpdot4((const float4*)(g_h + b*HH),
                               (const float4*)(sW1 + (size_t)w*HH), HH/4) + sb1[w];
            if ((tid & 31) == 0) g_pred[w] = s;
        }
    }
    grid_bar(2);

    // ---------------- S3: p GEMM (144, A=silu(h1), splitK12) + out (spare) ----------------
    if (bid < 144) {
        int kc = bid % 12, tile = bid / 12;
        int bb = tile / 6, tc = tile % 6;
        int n0 = tc*64, k0 = kc*64;
        const float* pa = g_h1 + (size_t)(bb*TT + r)*HH + k0 + ks;
        const float* pb = sW1 + (size_t)(bb*CC + n0 + r)*HH + k0 + ks;
        float4 ra = *(const float4*)pa, rb = *(const float4*)pb;
        sts4(As[0], r, ks, make_float4(silu_f(ra.x), silu_f(ra.y), silu_f(ra.z), silu_f(ra.w)));
        sts4(Bs[0], r, ks, rb);
        __syncthreads();
        float acc[4][4] = {};
        #pragma unroll
        for (int kt = 0; kt < 4; ++kt) {
            if (kt < 3) { ra = *(const float4*)(pa + (kt+1)*BKt);
                          rb = *(const float4*)(pb + (kt+1)*BKt); }
            core16(As[kt&1], Bs[kt&1], acc, tm, tn);
            if (kt < 3) {
                sts4(As[(kt+1)&1], r, ks,
                     make_float4(silu_f(ra.x), silu_f(ra.y), silu_f(ra.z), silu_f(ra.w)));
                sts4(Bs[(kt+1)&1], r, ks, rb);
            }
            __syncthreads();
        }
        #pragma unroll
        for (int i = 0; i < 4; ++i) {
            int m = tm*4 + i;
            #pragma unroll
            for (int j = 0; j < 4; ++j)
                atomicAdd(&g_dp[(size_t)(bb*TT + m)*CC + n0 + tn*4 + j], acc[i][j]);
        }
    } else {            // out: 768 dots, K=384
        int w = (bid - 144)*8 + (tid >> 5);
        if (w < BB*CC) {
            int b = w / CC, c = w % CC;
            float s = warpdot4((const float4*)(g_pred + b*CC),
                               (const float4*)(Wo + (size_t)c*CC), CC/4) + bo[c];
            if ((tid & 31) == 0) o_out[w] = s;
        }
    }
    grid_bar(3);

    // ---------------- S4: ds GEMM = (p - v) @ sW1, all 288 blocks, splitK12 ----------------
    {
        int kc = bid % 12, tile = bid / 12;
        int bb = tile / 12, tc = tile % 12;
        int n0 = tc*64, k0 = kc*32;
        int kkb = tid >> 4, cs = (tid & 15) << 2;
        const float* pap = g_dp + (size_t)(bb*TT + r)*CC + k0 + ks;
        const float* pav = g_v  + (size_t)(bb*TT + r)*CC + k0 + ks;
        const float* pb  = sW1 + (size_t)(bb*CC + k0 + kkb)*HH + n0 + cs;
        float4 rp = *(const float4*)pap, rv = *(const float4*)pav;
        float4 rb = *(const float4*)pb;
        sts4(As[0], r, ks, make_float4(rp.x - rv.x, rp.y - rv.y, rp.z - rv.z, rp.w - rv.w));
        *(float4*)&Bs[0][kkb][cs] = rb;
        __syncthreads();
        float acc[4][4] = {};
        #pragma unroll
        for (int kt = 0; kt < 2; ++kt) {
            if (kt < 1) { rp = *(const float4*)(pap + BKt);
                          rv = *(const float4*)(pav + BKt);
                          rb = *(const float4*)(pb + (size_t)BKt*HH); }
            core16(As[kt&1], Bs[kt&1], acc, tm, tn);
            if (kt < 1) {
                sts4(As[1], r, ks, make_float4(rp.x - rv.x, rp.y - rv.y, rp.z - rv.z, rp.w - rv.w));
                *(float4*)&Bs[1][kkb][cs] = rb;
            }
            __syncthreads();
        }
        #pragma unroll
        for (int i = 0; i < 4; ++i) {
            int m = tm*4 + i;
            #pragma unroll
            for (int j = 0; j < 4; ++j)
                atomicAdd(&g_ds[(size_t)(bb*TT + m)*HH + n0 + tn*4 + j], acc[i][j]);
        }
    }
    grid_bar(4);

    // ---------------- S5: nW0 (144) + nW1 (144), nb folded into tc==0 tiles ----------------
    {
        if (tid < TT) {
            double d = 0.999, rr_ = 0.9 / 0.999;
            double csm = pow(d, (double)(TT-1-tid)) * (pow(rr_, (double)(TT-tid)) - 1.0)
                         / (rr_ - 1.0);
            coeff_s[tid] = (float)(-0.01 * 0.1 * csm);
        }
        __syncthreads();
        const float df = (float)pow(0.999, (double)TT);

        bool is0 = bid < 144;
        int tile = is0 ? bid : bid - 144;
        int bb = tile / 72, rr = tile % 72;
        int tr = is0 ? rr/6 : rr/12;
        int tc = is0 ? rr%6 : rr%12;
        int m0 = tr*64, n0 = tc*64;
        int kk = tid >> 4, ms = (tid & 15) << 2;
        float4 r1, r2, r3;
        float csum[4] = {0.f, 0.f, 0.f, 0.f};

        #define LD_SLAB(kt) do {                                                   \
            int t_ = (kt)*BKt + kk;                                                \
            if (is0) {                                                             \
                size_t ia = (size_t)(bb*TT + t_)*HH + m0 + ms;                     \
                r1 = *(const float4*)&g_ds[ia];                                    \
                r2 = *(const float4*)&g_h1[ia];                                    \
                r3 = *(const float4*)&g_k[(size_t)(bb*TT + t_)*CC + n0 + ms];      \
            } else {                                                               \
                size_t ia = (size_t)(bb*TT + t_)*CC + m0 + ms;                     \
                float4 pp = *(const float4*)&g_dp[ia];                             \
                float4 vv = *(const float4*)&g_v[ia];                              \
                r1 = make_float4(pp.x - vv.x, pp.y - vv.y, pp.z - vv.z, pp.w - vv.w);\
                r2 = *(const float4*)&g_h1[(size_t)(bb*TT + t_)*HH + n0 + ms];     \
            }                                                                      \
        } while (0)
        #define ST_SLAB(buf, kt) do {                                              \
            int t_ = (kt)*BKt + kk;                                                \
            float cf = coeff_s[t_];                                                \
            float a0, a1, a2, a3;                                                  \
            if (is0) {                                                             \
                a0 = cf * r1.x * gfac_f(r2.x); a1 = cf * r1.y * gfac_f(r2.y);      \
                a2 = cf * r1.z * gfac_f(r2.z); a3 = cf * r1.w * gfac_f(r2.w);      \
                *(float4*)&Bs[buf][kk][ms] = r3;                                   \
            } else {                                                               \
                a0 = cf * r1.x; a1 = cf * r1.y; a2 = cf * r1.z; a3 = cf * r1.w;    \
                Bs[buf][kk][ms+0] = silu_f(r2.x); Bs[buf][kk][ms+1] = silu_f(r2.y);\
                Bs[buf][kk][ms+2] = silu_f(r2.z); Bs[buf][kk][ms+3] = silu_f(r2.w);\
            }                                                                      \
            As[buf][kk][ms+0] = a0; As[buf][kk][ms+1] = a1;                        \
            As[buf][kk][ms+2] = a2; As[buf][kk][ms+3] = a3;                        \
            csum[0] += a0; csum[1] += a1; csum[2] += a2; csum[3] += a3;            \
        } while (0)

        LD_SLAB(0); ST_SLAB(0, 0);
        __syncthreads();
        float acc[4][4] = {};
        #pragma unroll
        for (int kt = 0; kt < 4; ++kt) {
            if (kt < 3) LD_SLAB(kt+1);
            core16(As[kt&1], Bs[kt&1], acc, tm, tn);
            if (kt < 3) ST_SLAB((kt+1)&1, kt+1);
            __syncthreads();
        }
        if (is0) {
            #pragma unroll
            for (int i = 0; i < 4; ++i) {
                int h = m0 + tm*4 + i;
                #pragma unroll
                for (int j = 0; j < 4; ++j) {
                    size_t idx = (size_t)(bb*HH + h)*CC + n0 + tn*4 + j;
                    o_nw0[idx] = df * sW0[idx] + acc[i][j];
                }
            }
        } else {
            #pragma unroll
            for (int i = 0; i < 4; ++i) {
                int c = m0 + tm*4 + i;
                #pragma unroll
                for (int j = 0; j < 4; ++j) {
                    size_t idx = (size_t)(bb*CC + c)*HH + n0 + tn*4 + j;
                    o_nw1[idx] = df * sW1[idx] + acc[i][j];
                }
            }
        }
        if (tc == 0) {   // fold biases: column sums of A
            if (tid < TT) red[tid] = 0.f;
            __syncthreads();
            atomicAdd(&red[ms+0], csum[0]); atomicAdd(&red[ms+1], csum[1]);
            atomicAdd(&red[ms+2], csum[2]); atomicAdd(&red[ms+3], csum[3]);
            __syncthreads();
            if (tid < TT) {
                if (is0) o_nb0[bb*HH + m0 + tid] = df * sb0[bb*HH + m0 + tid] + red[tid];
                else     o_nb1[bb*CC + m0 + tid] = df * sb1[bb*CC + m0 + tid] + red[tid];
            }
        }
    }
}

// ============================================================================
extern "C" void kernel_launch(void* const* d_in, const int* in_sizes, int n_in,
                              void* d_out, int out_size) {
    const float* x   = (const float*)d_in[0];
    const float* Wq  = (const float*)d_in[1];
    const float* bq  = (const float*)d_in[2];
    const float* Wk  = (const float*)d_in[3];
    const float* bk  = (const float*)d_in[4];
    const float* Wv  = (const float*)d_in[5];
    const float* bv  = (const float*)d_in[6];
    const float* Wo  = (const float*)d_in[7];
    const float* bo  = (const float*)d_in[8];
    const float* iq  = (const float*)d_in[9];
    const float* sW0 = (const float*)d_in[10];
    const float* sb0 = (const float*)d_in[11];
    const float* sW1 = (const float*)d_in[12];
    const float* sb1 = (const float*)d_in[13];

    float* out   = (float*)d_out;
    float* o_out = out;
    float* o_nw0 = o_out + BB*CC;
    float* o_nb0 = o_nw0 + (size_t)BB*HH*CC;
    float* o_nw1 = o_nb0 + BB*HH;
    float* o_nb1 = o_nw1 + (size_t)BB*CC*HH;

    fused<<<NB, 256>>>(x, Wq, bq, Wk, bk, Wv, bv, Wo, bo, iq, sW0, sb0, sW1, sb1,
                       o_out, o_nw0, o_nb0, o_nw1, o_nb1);
}

// round 11
// speedup vs baseline: 1.6088x; 1.1081x over previous
#include <cuda_runtime.h>
#include <cuda_bf16.h>
#include <math.h>

#define BB 2
#define TT 64
#define CC 384
#define HH 768
#define BKt 16
#define LDA_S 68
#define NB 288
#define KVN (128*768)    // one k||v part buffer: [B*T=128][768]

// ---------------- scratch (device globals) ----------------
#define N_KV (BB*TT*CC)   // 49152
#define N_H  (BB*TT*HH)   // 98304
__device__ float g_kvp[6*KVN];  // splitK parts of k||v (plain stores, no init)
__device__ float g_k[N_KV];     // finalized k (S2 spares)
__device__ float g_v[N_KV];     // finalized v (S2 spares)
__device__ float g_dp[N_KV];    // holds p; consumers do p - v
__device__ float g_h1[N_H];     // layer-1 pre-activation (bias included)
__device__ float g_ds[N_H];     // (p-v) @ W1
__device__ float g_q[CC];
__device__ float g_h[BB*HH];
__device__ float g_pred[BB*CC];
__device__ unsigned g_bar[8];   // monotonic tickets, never reset

__device__ __forceinline__ float silu_f(float x) {
    float s = 1.f / (1.f + expf(-x)); return x * s;
}
__device__ __forceinline__ float gfac_f(float x) {
    float s = 1.f / (1.f + expf(-x)); return s * (1.f + x * (1.f - s));
}

__device__ __forceinline__ void grid_bar(int which) {
    __syncthreads();
    if (threadIdx.x == 0) {
        unsigned* p = &g_bar[which];
        unsigned ticket;
        asm volatile("atom.release.gpu.global.add.u32 %0, [%1], 1;"
                     : "=r"(ticket) : "l"(p) : "memory");
        unsigned target = ticket - (ticket % NB) + NB;
        unsigned cur;
        do {
            __nanosleep(32);
            asm volatile("ld.acquire.gpu.global.u32 %0, [%1];"
                         : "=r"(cur) : "l"(p) : "memory");
        } while ((int)(cur - target) < 0);
    }
    __syncthreads();
}

__device__ __forceinline__ float warpdot4(const float4* a, const float4* b, int n4) {
    float s = 0.f;
    for (int i = (threadIdx.x & 31); i < n4; i += 32) {
        float4 x = a[i], y = b[i];
        s += x.x*y.x + x.y*y.y + x.z*y.z + x.w*y.w;
    }
    #pragma unroll
    for (int o = 16; o; o >>= 1) s += __shfl_xor_sync(0xFFFFFFFFu, s, o);
    return s;
}

__device__ __forceinline__ void core16(const float (*As)[LDA_S], const float (*Bs)[LDA_S],
                                       float (&acc)[4][4], int tm, int tn) {
    #pragma unroll
    for (int kk = 0; kk < BKt; ++kk) {
        float4 a4 = *(const float4*)&As[kk][tm*4];
        float4 b4 = *(const float4*)&Bs[kk][tn*4];
        float av[4] = {a4.x, a4.y, a4.z, a4.w};
        float bv[4] = {b4.x, b4.y, b4.z, b4.w};
        #pragma unroll
        for (int i = 0; i < 4; ++i)
            #pragma unroll
            for (int j = 0; j < 4; ++j)
                acc[i][j] += av[i] * bv[j];
    }
}

__device__ __forceinline__ void sts4(float (*S)[LDA_S], int r, int ks, float4 v) {
    S[ks+0][r] = v.x; S[ks+1][r] = v.y; S[ks+2][r] = v.z; S[ks+3][r] = v.w;
}

// sum the 6 k||v parts at a flat [row*768+col] offset
__device__ __forceinline__ float4 sum_parts(size_t off) {
    float4 s = make_float4(0.f, 0.f, 0.f, 0.f);
    #pragma unroll
    for (int p = 0; p < 6; ++p) {
        float4 t = *(const float4*)&g_kvp[(size_t)p*KVN + off];
        s.x += t.x; s.y += t.y; s.z += t.z; s.w += t.w;
    }
    return s;
}

// ============================================================================
__global__ void __launch_bounds__(256, 2)
fused(const float* __restrict__ x,   const float* __restrict__ Wq,
      const float* __restrict__ bq,  const float* __restrict__ Wk,
      const float* __restrict__ bk,  const float* __restrict__ Wv,
      const float* __restrict__ bv,  const float* __restrict__ Wo,
      const float* __restrict__ bo,  const float* __restrict__ iq,
      const float* __restrict__ sW0, const float* __restrict__ sb0,
      const float* __restrict__ sW1, const float* __restrict__ sb1,
      float* __restrict__ o_out, float* __restrict__ o_nw0,
      float* __restrict__ o_nb0, float* __restrict__ o_nw1,
      float* __restrict__ o_nb1)
{
    __shared__ float As[2][BKt][LDA_S];
    __shared__ float Bs[2][BKt][LDA_S];
    __shared__ float red[TT];
    __shared__ float coeff_s[TT];

    const int bid = blockIdx.x, tid = threadIdx.x;
    const int r  = tid >> 2, ks = (tid & 3) << 2;   // transpose-load role
    const int tm = tid & 15, tn = tid >> 4;          // micro-tile role

    // ======== S1: kv GEMM parts (144) | inits + q + bias-part (144) ========
    if (bid < 144) {
        int kc = bid % 6, tile = bid / 6;
        int tr = tile / 12, tc = tile % 12;
        int m0 = tr*64, n0 = tc*64, k0 = kc*64;
        const float* Wn = (n0 < CC) ? Wk + (size_t)n0*CC : Wv + (size_t)(n0-CC)*CC;
        const float* pa = x  + (size_t)(m0 + r)*CC + k0 + ks;
        const float* pb = Wn + (size_t)r*CC       + k0 + ks;
        float4 ra = *(const float4*)pa, rb = *(const float4*)pb;
        sts4(As[0], r, ks, ra); sts4(Bs[0], r, ks, rb);
        __syncthreads();
        float acc[4][4] = {};
        #pragma unroll
        for (int kt = 0; kt < 4; ++kt) {
            if (kt < 3) { ra = *(const float4*)(pa + (kt+1)*BKt);
                          rb = *(const float4*)(pb + (kt+1)*BKt); }
            core16(As[kt&1], Bs[kt&1], acc, tm, tn);
            if (kt < 3) { sts4(As[(kt+1)&1], r, ks, ra); sts4(Bs[(kt+1)&1], r, ks, rb); }
            __syncthreads();
        }
        // add bias once (kc==0) so parts sum to final k||v
        float4 badd = make_float4(0.f, 0.f, 0.f, 0.f);
        if (kc == 0) {
            int c = n0 + tn*4;
            const float* bsrc = (n0 < CC) ? bk + c : bv + (c - CC);
            badd = make_float4(bsrc[0], bsrc[1], bsrc[2], bsrc[3]);
        }
        float* dst = g_kvp + (size_t)kc*KVN;
        #pragma unroll
        for (int i = 0; i < 4; ++i) {
            int m = m0 + tm*4 + i;
            *(float4*)&dst[(size_t)m*768 + n0 + tn*4] =
                make_float4(acc[i][0]+badd.x, acc[i][1]+badd.y,
                            acc[i][2]+badd.z, acc[i][3]+badd.w);
        }
    } else {
        // distributed init of atomic targets (needed one stage later)
        int gt = (bid - 144)*256 + tid;            // 0..36863
        for (int i = gt; i < N_H; i += 144*256) {
            g_h1[i] = sb0[(i/(TT*HH))*HH + (i % HH)];
            g_ds[i] = 0.f;
        }
        for (int i = gt; i < N_KV; i += 144*256)
            g_dp[i] = sb1[(i/(TT*CC))*CC + (i % CC)];
        if (bid >= 240) {   // q: 384 dots, K=384
            int w = (bid - 240)*8 + (tid >> 5);
            float s = warpdot4((const float4*)iq, (const float4*)(Wq + (size_t)w*CC), CC/4);
            if ((tid & 31) == 0) g_q[w] = s + bq[w];
        }
    }
    grid_bar(0);

    // ======== S2: h1pre GEMM from parts (144) | h dots + finalize k,v (144) ========
    if (bid < 144) {
        int kc = bid % 6, tile = bid / 6;
        int bb = tile / 12, tc = tile % 12;
        int n0 = tc*64, k0 = kc*64;
        size_t abase = (size_t)(bb*64 + r)*768 + k0 + ks;   // k cols 0..383
        const float* pb = sW0 + (size_t)(bb*HH + n0 + r)*CC + k0 + ks;
        float4 ra = sum_parts(abase);
        float4 rb = *(const float4*)pb;
        sts4(As[0], r, ks, ra); sts4(Bs[0], r, ks, rb);
        __syncthreads();
        float acc[4][4] = {};
        #pragma unroll
        for (int kt = 0; kt < 4; ++kt) {
            if (kt < 3) { ra = sum_parts(abase + (kt+1)*BKt);
                          rb = *(const float4*)(pb + (kt+1)*BKt); }
            core16(As[kt&1], Bs[kt&1], acc, tm, tn);
            if (kt < 3) { sts4(As[(kt+1)&1], r, ks, ra); sts4(Bs[(kt+1)&1], r, ks, rb); }
            __syncthreads();
        }
        #pragma unroll
        for (int i = 0; i < 4; ++i) {
            int m = tm*4 + i;
            #pragma unroll
            for (int j = 0; j < 4; ++j)
                atomicAdd(&g_h1[(size_t)(bb*TT + m)*HH + n0 + tn*4 + j], acc[i][j]);
        }
    } else {
        // finalize k and v for S4/S5 consumers
        int gt = (bid - 144)*256 + tid;
        for (int i4 = gt; i4 < N_KV/4; i4 += 144*256) {    // 12288
            int row = i4 / 96, c4 = (i4 % 96) * 4;
            size_t base = (size_t)row*768 + c4;
            *(float4*)&g_k[(size_t)row*CC + c4] = sum_parts(base);
            *(float4*)&g_v[(size_t)row*CC + c4] = sum_parts(base + 384);
        }
        // h: 1536 dots K=384
        for (int w = (bid - 144)*8 + (tid >> 5); w < BB*HH; w += 144*8) {
            float s = warpdot4((const float4*)g_q, (const float4*)(sW0 + (size_t)w*CC),
                               CC/4) + sb0[w];
            if ((tid & 31) == 0) g_h[w] = silu_f(s);
        }
    }
    grid_bar(1);

    // ======== S3: p GEMM, A=silu(h1), splitK12 (144) | pred dots (144) ========
    if (bid < 144) {
        int kc = bid % 12, tile = bid / 12;
        int bb = tile / 6, tc = tile % 6;
        int n0 = tc*64, k0 = kc*64;
        const float* pa = g_h1 + (size_t)(bb*TT + r)*HH + k0 + ks;
        const float* pb = sW1 + (size_t)(bb*CC + n0 + r)*HH + k0 + ks;
        float4 ra = *(const float4*)pa, rb = *(const float4*)pb;
        sts4(As[0], r, ks, make_float4(silu_f(ra.x), silu_f(ra.y), silu_f(ra.z), silu_f(ra.w)));
        sts4(Bs[0], r, ks, rb);
        __syncthreads();
        float acc[4][4] = {};
        #pragma unroll
        for (int kt = 0; kt < 4; ++kt) {
            if (kt < 3) { ra = *(const float4*)(pa + (kt+1)*BKt);
                          rb = *(const float4*)(pb + (kt+1)*BKt); }
            core16(As[kt&1], Bs[kt&1], acc, tm, tn);
            if (kt < 3) {
                sts4(As[(kt+1)&1], r, ks,
                     make_float4(silu_f(ra.x), silu_f(ra.y), silu_f(ra.z), silu_f(ra.w)));
                sts4(Bs[(kt+1)&1], r, ks, rb);
            }
            __syncthreads();
        }
        #pragma unroll
        for (int i = 0; i < 4; ++i) {
            int m = tm*4 + i;
            #pragma unroll
            for (int j = 0; j < 4; ++j)
                atomicAdd(&g_dp[(size_t)(bb*TT + m)*CC + n0 + tn*4 + j], acc[i][j]);
        }
    } else {            // pred: 768 dots K=768
        int w = (bid - 144)*8 + (tid >> 5);
        if (w < BB*CC) {
            int b = w / CC;
            float s = warpdot4((const float4*)(g_h + b*HH),
                               (const float4*)(sW1 + (size_t)w*HH), HH/4) + sb1[w];
            if ((tid & 31) == 0) g_pred[w] = s;
        }
    }
    grid_bar(2);

    // ======== S4: ds GEMM = (p - v) @ sW1, all 288, splitK12; out dots appended ========
    {
        int kc = bid % 12, tile = bid / 12;
        int bb = tile / 12, tc = tile % 12;
        int n0 = tc*64, k0 = kc*32;
        int kkb = tid >> 4, cs = (tid & 15) << 2;
        const float* pap = g_dp + (size_t)(bb*TT + r)*CC + k0 + ks;
        const float* pav = g_v  + (size_t)(bb*TT + r)*CC + k0 + ks;
        const float* pb  = sW1 + (size_t)(bb*CC + k0 + kkb)*HH + n0 + cs;
        float4 rp = *(const float4*)pap, rv = *(const float4*)pav;
        float4 rb = *(const float4*)pb;
        sts4(As[0], r, ks, make_float4(rp.x - rv.x, rp.y - rv.y, rp.z - rv.z, rp.w - rv.w));
        *(float4*)&Bs[0][kkb][cs] = rb;
        __syncthreads();
        float acc[4][4] = {};
        #pragma unroll
        for (int kt = 0; kt < 2; ++kt) {
            if (kt < 1) { rp = *(const float4*)(pap + BKt);
                          rv = *(const float4*)(pav + BKt);
                          rb = *(const float4*)(pb + (size_t)BKt*HH); }
            core16(As[kt&1], Bs[kt&1], acc, tm, tn);
            if (kt < 1) {
                sts4(As[1], r, ks, make_float4(rp.x - rv.x, rp.y - rv.y, rp.z - rv.z, rp.w - rv.w));
                *(float4*)&Bs[1][kkb][cs] = rb;
            }
            __syncthreads();
        }
        #pragma unroll
        for (int i = 0; i < 4; ++i) {
            int m = tm*4 + i;
            #pragma unroll
            for (int j = 0; j < 4; ++j)
                atomicAdd(&g_ds[(size_t)(bb*TT + m)*HH + n0 + tn*4 + j], acc[i][j]);
        }
        // out dots overlap the REDG drain: 768 dots K=384 on blocks 0-95
        if (bid < 96) {
            int w = bid*8 + (tid >> 5);
            int b = w / CC, c = w % CC;
            float s = warpdot4((const float4*)(g_pred + b*CC),
                               (const float4*)(Wo + (size_t)c*CC), CC/4) + bo[c];
            if ((tid & 31) == 0) o_out[w] = s;
        }
    }
    grid_bar(3);

    // ======== S5: nW0 (144) + nW1 (144), biases folded into tc==0 tiles ========
    {
        if (tid < TT) {
            double d = 0.999, rr_ = 0.9 / 0.999;
            double csm = pow(d, (double)(TT-1-tid)) * (pow(rr_, (double)(TT-tid)) - 1.0)
                         / (rr_ - 1.0);
            coeff_s[tid] = (float)(-0.01 * 0.1 * csm);
        }
        __syncthreads();
        const float df = (float)pow(0.999, (double)TT);

        bool is0 = bid < 144;
        int tile = is0 ? bid : bid - 144;
        int bb = tile / 72, rr = tile % 72;
        int tr = is0 ? rr/6 : rr/12;
        int tc = is0 ? rr%6 : rr%12;
        int m0 = tr*64, n0 = tc*64;
        int kk = tid >> 4, ms = (tid & 15) << 2;
        float4 r1, r2, r3;
        float csum[4] = {0.f, 0.f, 0.f, 0.f};

        #define LD_SLAB(kt) do {                                                   \
            int t_ = (kt)*BKt + kk;                                                \
            if (is0) {                                                             \
                size_t ia = (size_t)(bb*TT + t_)*HH + m0 + ms;                     \
                r1 = *(const float4*)&g_ds[ia];                                    \
                r2 = *(const float4*)&g_h1[ia];                                    \
                r3 = *(const float4*)&g_k[(size_t)(bb*TT + t_)*CC + n0 + ms];      \
            } else {                                                               \
                size_t ia = (size_t)(bb*TT + t_)*CC + m0 + ms;                     \
                float4 pp = *(const float4*)&g_dp[ia];                             \
                float4 vv = *(const float4*)&g_v[ia];                              \
                r1 = make_float4(pp.x - vv.x, pp.y - vv.y, pp.z - vv.z, pp.w - vv.w);\
                r2 = *(const float4*)&g_h1[(size_t)(bb*TT + t_)*HH + n0 + ms];     \
            }                                                                      \
        } while (0)
        #define ST_SLAB(buf, kt) do {                                              \
            int t_ = (kt)*BKt + kk;                                                \
            float cf = coeff_s[t_];                                                \
            float a0, a1, a2, a3;                                                  \
            if (is0) {                                                             \
                a0 = cf * r1.x * gfac_f(r2.x); a1 = cf * r1.y * gfac_f(r2.y);      \
                a2 = cf * r1.z * gfac_f(r2.z); a3 = cf * r1.w * gfac_f(r2.w);      \
                *(float4*)&Bs[buf][kk][ms] = r3;                                   \
            } else {                                                               \
                a0 = cf * r1.x; a1 = cf * r1.y; a2 = cf * r1.z; a3 = cf * r1.w;    \
                Bs[buf][kk][ms+0] = silu_f(r2.x); Bs[buf][kk][ms+1] = silu_f(r2.y);\
                Bs[buf][kk][ms+2] = silu_f(r2.z); Bs[buf][kk][ms+3] = silu_f(r2.w);\
            }                                                                      \
            As[buf][kk][ms+0] = a0; As[buf][kk][ms+1] = a1;                        \
            As[buf][kk][ms+2] = a2; As[buf][kk][ms+3] = a3;                        \
            csum[0] += a0; csum[1] += a1; csum[2] += a2; csum[3] += a3;            \
        } while (0)

        LD_SLAB(0); ST_SLAB(0, 0);
        __syncthreads();
        float acc[4][4] = {};
        #pragma unroll
        for (int kt = 0; kt < 4; ++kt) {
            if (kt < 3) LD_SLAB(kt+1);
            core16(As[kt&1], Bs[kt&1], acc, tm, tn);
            if (kt < 3) ST_SLAB((kt+1)&1, kt+1);
            __syncthreads();
        }
        if (is0) {
            #pragma unroll
            for (int i = 0; i < 4; ++i) {
                int h = m0 + tm*4 + i;
                #pragma unroll
                for (int j = 0; j < 4; ++j) {
                    size_t idx = (size_t)(bb*HH + h)*CC + n0 + tn*4 + j;
                    o_nw0[idx] = df * sW0[idx] + acc[i][j];
                }
            }
        } else {
            #pragma unroll
            for (int i = 0; i < 4; ++i) {
                int c = m0 + tm*4 + i;
                #pragma unroll
                for (int j = 0; j < 4; ++j) {
                    size_t idx = (size_t)(bb*CC + c)*HH + n0 + tn*4 + j;
                    o_nw1[idx] = df * sW1[idx] + acc[i][j];
                }
            }
        }
        if (tc == 0) {   // fold biases: column sums of A
            if (tid < TT) red[tid] = 0.f;
            __syncthreads();
            atomicAdd(&red[ms+0], csum[0]); atomicAdd(&red[ms+1], csum[1]);
            atomicAdd(&red[ms+2], csum[2]); atomicAdd(&red[ms+3], csum[3]);
            __syncthreads();
            if (tid < TT) {
                if (is0) o_nb0[bb*HH + m0 + tid] = df * sb0[bb*HH + m0 + tid] + red[tid];
                else     o_nb1[bb*CC + m0 + tid] = df * sb1[bb*CC + m0 + tid] + red[tid];
            }
        }
    }
}

// ============================================================================
extern "C" void kernel_launch(void* const* d_in, const int* in_sizes, int n_in,
                              void* d_out, int out_size) {
    const float* x   = (const float*)d_in[0];
    const float* Wq  = (const float*)d_in[1];
    const float* bq  = (const float*)d_in[2];
    const float* Wk  = (const float*)d_in[3];
    const float* bk  = (const float*)d_in[4];
    const float* Wv  = (const float*)d_in[5];
    const float* bv  = (const float*)d_in[6];
    const float* Wo  = (const float*)d_in[7];
    const float* bo  = (const float*)d_in[8];
    const float* iq  = (const float*)d_in[9];
    const float* sW0 = (const float*)d_in[10];
    const float* sb0 = (const float*)d_in[11];
    const float* sW1 = (const float*)d_in[12];
    const float* sb1 = (const float*)d_in[13];

    float* out   = (float*)d_out;
    float* o_out = out;
    float* o_nw0 = o_out + BB*CC;
    float* o_nb0 = o_nw0 + (size_t)BB*HH*CC;
    float* o_nw1 = o_nb0 + BB*HH;
    float* o_nb1 = o_nw1 + (size_t)BB*CC*HH;

    fused<<<NB, 256>>>(x, Wq, bq, Wk, bk, Wv, bv, Wo, bo, iq, sW0, sb0, sW1, sb1,
                       o_out, o_nw0, o_nb0, o_nw1, o_nb1);
}